// round 17
// baseline (speedup 1.0000x reference)
#include <cuda_runtime.h>
#include <cuda_bf16.h>
#include <cstdint>

// Problem constants
#define T_SEQ 512
#define B_SZ  64
#define E_SZ  512
#define G3E   1536
#define M_ROWS (T_SEQ * B_SZ)

// ---------------- device scratch ----------------
__device__ float g_x[T_SEQ * B_SZ * E_SZ];
__device__ float g_xproj[T_SEQ * B_SZ * G3E];
__device__ float g_h[B_SZ * E_SZ];
__device__ unsigned g_step[128];                              // R13 counters
__device__ __align__(16) __nv_bfloat16 g_axhi[M_ROWS * E_SZ]; // activation hi
__device__ __align__(16) __nv_bfloat16 g_axlo[M_ROWS * E_SZ]; // activation lo
__device__ __align__(16) __nv_bfloat16 g_whi[G3E * E_SZ];     // W_ih hi (layer)
__device__ __align__(16) __nv_bfloat16 g_wlo[G3E * E_SZ];     // W_ih lo (layer)

// ---------------- f32x2 helpers ----------------
__device__ __forceinline__ void fma2(unsigned long long& d, unsigned long long a,
                                     unsigned long long b) {
    asm("fma.rn.f32x2 %0, %1, %2, %3;" : "=l"(d) : "l"(a), "l"(b), "l"(d));
}
__device__ __forceinline__ float f32x2_sum(unsigned long long v) {
    return __uint_as_float((unsigned)v) + __uint_as_float((unsigned)(v >> 32));
}

// ---------------- counter primitives ----------------
__device__ __forceinline__ void ctr_release_add(unsigned* ctr) {
    asm volatile("red.release.gpu.global.add.u32 [%0], %1;" :: "l"(ctr), "r"(1u) : "memory");
}
__device__ __forceinline__ void ctr_wait(unsigned* ctr, unsigned target) {
    unsigned cur;
    do {
        asm volatile("ld.acquire.gpu.u32 %0, [%1];" : "=r"(cur) : "l"(ctr) : "memory");
    } while ((int)(cur - target) < 0);
}

// ---------------- mma.sync / ldmatrix helpers (portable sm_80+) ----------------
__device__ __forceinline__ uint32_t smem_u32(const void* p) {
    uint32_t a;
    asm("{ .reg .u64 t; cvta.to.shared.u64 t, %1; cvt.u32.u64 %0, t; }" : "=r"(a) : "l"(p));
    return a;
}
__device__ __forceinline__ void ldsm4(uint32_t* r, uint32_t addr) {
    asm volatile("ldmatrix.sync.aligned.m8n8.x4.shared.b16 {%0,%1,%2,%3}, [%4];"
                 : "=r"(r[0]), "=r"(r[1]), "=r"(r[2]), "=r"(r[3]) : "r"(addr));
}
__device__ __forceinline__ void mma_bf16(float* c, const uint32_t* a, const uint32_t* b) {
    asm volatile(
        "mma.sync.aligned.m16n8k16.row.col.f32.bf16.bf16.f32 "
        "{%0,%1,%2,%3}, {%4,%5,%6,%7}, {%8,%9}, {%0,%1,%2,%3};"
        : "+f"(c[0]), "+f"(c[1]), "+f"(c[2]), "+f"(c[3])
        : "r"(a[0]), "r"(a[1]), "r"(a[2]), "r"(a[3]), "r"(b[0]), "r"(b[1]));
}

// ---------------- embedding gather (+ counter reset) ----------------
__global__ void embed_kernel(const int* __restrict__ idx,
                             const float* __restrict__ emb,
                             float* __restrict__ out) {
    if (blockIdx.x == 0 && threadIdx.x < 128) g_step[threadIdx.x] = 0u;
    int i = blockIdx.x * blockDim.x + threadIdx.x;
    const int total = T_SEQ * B_SZ * (E_SZ / 4);
    if (i >= total) return;
    int row = i >> 7;
    int col = i & 127;
    int tok = idx[row];
    reinterpret_cast<float4*>(out)[i] =
        reinterpret_cast<const float4*>(emb)[(size_t)tok * 128 + col];
}

// ---------------- fp32 -> bf16 hi/lo split ----------------
__global__ void split_kernel(const float* __restrict__ src,
                             __nv_bfloat16* __restrict__ hi,
                             __nv_bfloat16* __restrict__ lo, int n4) {
    int i = blockIdx.x * blockDim.x + threadIdx.x;
    if (i >= n4) return;
    float4 v = reinterpret_cast<const float4*>(src)[i];
    __nv_bfloat16 h0 = __float2bfloat16(v.x), h1 = __float2bfloat16(v.y);
    __nv_bfloat16 h2 = __float2bfloat16(v.z), h3 = __float2bfloat16(v.w);
    __nv_bfloat16 l0 = __float2bfloat16(v.x - __bfloat162float(h0));
    __nv_bfloat16 l1 = __float2bfloat16(v.y - __bfloat162float(h1));
    __nv_bfloat16 l2 = __float2bfloat16(v.z - __bfloat162float(h2));
    __nv_bfloat16 l3 = __float2bfloat16(v.w - __bfloat162float(h3));
    reinterpret_cast<__nv_bfloat162*>(hi)[2 * i]     = __halves2bfloat162(h0, h1);
    reinterpret_cast<__nv_bfloat162*>(hi)[2 * i + 1] = __halves2bfloat162(h2, h3);
    reinterpret_cast<__nv_bfloat162*>(lo)[2 * i]     = __halves2bfloat162(l0, l1);
    reinterpret_cast<__nv_bfloat162*>(lo)[2 * i + 1] = __halves2bfloat162(l2, l3);
}

// ---------------- tensor-core GEMM via mma.sync bf16 + bf16x3 split ----------------
// C[M,G3E] = A*B^T + bias. 128x128 CTA tile, BK=32, 256 thr = 8 warps (4m x 2n),
// warp tile 32x64. Smem rows padded to 40 bf16 (80B) -> conflict-free ldmatrix.
#define TCBK 32
#define SROW 40                       // bf16 per smem row (80 B)
#define STILE (128 * SROW)            // 5120 bf16 per tile

__global__ __launch_bounds__(256) void tc_gemm(
    const __nv_bfloat16* __restrict__ Ahi, const __nv_bfloat16* __restrict__ Alo,
    const __nv_bfloat16* __restrict__ Bhi, const __nv_bfloat16* __restrict__ Blo,
    const float* __restrict__ bias, float* __restrict__ C) {
    __shared__ __nv_bfloat16 sAhi[STILE], sAlo[STILE], sBhi[STILE], sBlo[STILE];

    const int tid = threadIdx.x;
    const int lane = tid & 31;
    const int warp = tid >> 5;
    const int bn = blockIdx.x * 128;
    const int bm = blockIdx.y * 128;
    const int mo = (warp & 3) * 32;   // warp M offset in tile
    const int no = (warp >> 2) * 64;  // warp N offset in tile

    // ldmatrix lane address components (bytes)
    // A x4: g0 rows0-7 b0 | g1 rows8-15 b0 | g2 rows0-7 b16 | g3 rows8-15 b16
    const int rowoff_a = ((lane >> 3) & 1) * 8 + (lane & 7);
    const int byteoff_a = (lane >> 4) * 16;
    // B x4: g0 n0-7 b0 | g1 n0-7 b16 | g2 n8-15 b0 | g3 n8-15 b16
    const int rowoff_b = (lane >> 4) * 8 + (lane & 7);
    const int byteoff_b = ((lane >> 3) & 1) * 16;

    const uint32_t sAhi_b = smem_u32(sAhi), sAlo_b = smem_u32(sAlo);
    const uint32_t sBhi_b = smem_u32(sBhi), sBlo_b = smem_u32(sBlo);

    float acc[2][8][4];
#pragma unroll
    for (int mt = 0; mt < 2; mt++)
#pragma unroll
        for (int nt = 0; nt < 8; nt++)
#pragma unroll
            for (int r = 0; r < 4; r++) acc[mt][nt][r] = 0.f;

    for (int k0 = 0; k0 < E_SZ; k0 += TCBK) {
        // stage 4 tiles of 128x32 bf16 (8KB each), 2 uint4 per thread per tile
#pragma unroll
        for (int p = 0; p < 2; p++) {
            int c = tid + p * 256;
            int row = c >> 2, c16 = c & 3;
            int soff = row * SROW + c16 * 8;
            size_t ga = (size_t)(bm + row) * E_SZ + k0 + c16 * 8;
            size_t gb = (size_t)(bn + row) * E_SZ + k0 + c16 * 8;
            *reinterpret_cast<uint4*>(&sAhi[soff]) = *reinterpret_cast<const uint4*>(&Ahi[ga]);
            *reinterpret_cast<uint4*>(&sAlo[soff]) = *reinterpret_cast<const uint4*>(&Alo[ga]);
            *reinterpret_cast<uint4*>(&sBhi[soff]) = *reinterpret_cast<const uint4*>(&Bhi[gb]);
            *reinterpret_cast<uint4*>(&sBlo[soff]) = *reinterpret_cast<const uint4*>(&Blo[gb]);
        }
        __syncthreads();

#pragma unroll
        for (int kq = 0; kq < 2; kq++) {         // two k16 steps per stage
            const int kb = kq * 32;              // byte offset of k16 within row

            uint32_t ah[2][4], al[2][4];
#pragma unroll
            for (int mt = 0; mt < 2; mt++) {
                uint32_t aoff = (uint32_t)((mo + mt * 16 + rowoff_a) * (SROW * 2)
                                           + kb + byteoff_a);
                ldsm4(ah[mt], sAhi_b + aoff);
                ldsm4(al[mt], sAlo_b + aoff);
            }
            uint32_t bh[8][2], bl[8][2];
#pragma unroll
            for (int ng = 0; ng < 4; ng++) {     // each x4 covers two n8 tiles
                uint32_t boff = (uint32_t)((no + ng * 16 + rowoff_b) * (SROW * 2)
                                           + kb + byteoff_b);
                uint32_t th[4], tl[4];
                ldsm4(th, sBhi_b + boff);
                ldsm4(tl, sBlo_b + boff);
                bh[2 * ng][0] = th[0]; bh[2 * ng][1] = th[1];
                bh[2 * ng + 1][0] = th[2]; bh[2 * ng + 1][1] = th[3];
                bl[2 * ng][0] = tl[0]; bl[2 * ng][1] = tl[1];
                bl[2 * ng + 1][0] = tl[2]; bl[2 * ng + 1][1] = tl[3];
            }

#pragma unroll
            for (int mt = 0; mt < 2; mt++)
#pragma unroll
                for (int nt = 0; nt < 8; nt++) {
                    mma_bf16(acc[mt][nt], ah[mt], bh[nt]);   // hi*hi
                    mma_bf16(acc[mt][nt], ah[mt], bl[nt]);   // hi*lo
                    mma_bf16(acc[mt][nt], al[mt], bh[nt]);   // lo*hi
                }
        }
        __syncthreads();
    }

    // epilogue: D m16n8 fragment -> C + bias
#pragma unroll
    for (int mt = 0; mt < 2; mt++) {
        int row = bm + mo + mt * 16 + (lane >> 2);
#pragma unroll
        for (int nt = 0; nt < 8; nt++) {
            int col = bn + no + nt * 8 + (lane & 3) * 2;
            float2 bv = *reinterpret_cast<const float2*>(&bias[col]);
            *reinterpret_cast<float2*>(&C[(size_t)row * G3E + col]) =
                make_float2(acc[mt][nt][0] + bv.x, acc[mt][nt][1] + bv.y);
            *reinterpret_cast<float2*>(&C[(size_t)(row + 8) * G3E + col]) =
                make_float2(acc[mt][nt][2] + bv.x, acc[mt][nt][3] + bv.y);
        }
    }
}

// ---------------- persistent GRU recurrence (exact R13) ----------------
#define RGRID 128
#define EGROUPS 16
#define BTILE 8
#define WROWS 96
#define WSTR 516
#define REGION_FLOATS 6144
#define RSMEM_FLOATS (WROWS * WSTR + REGION_FLOATS)
#define RSMEM_BYTES (RSMEM_FLOATS * 4)      // 222,720 B

__global__ __launch_bounds__(256, 1) void gru_recur_kernel(
    const float* __restrict__ xproj,
    const float* __restrict__ Whh,
    const float* __restrict__ bhh,
    const int* __restrict__ lens,
    float* __restrict__ hbuf,
    float* __restrict__ ybuf,
    float* __restrict__ finals,
    int epoch)
{
    extern __shared__ float smemf[];
    float* sh_w = smemf;
    float* sh_h = smemf + WROWS * WSTR;
    float* sh_part = sh_h;

    const int tid = threadIdx.x;
    const int cta = blockIdx.x;
    const int bg = cta / EGROUPS;
    const int eg = cta % EGROUPS;
    const int ebase = eg * 32;
    const int w = tid >> 5;
    const int jg = tid & 31;
    const int bglob = bg * BTILE + w;
    const int e = ebase + jg;
    const int kbase = w * 64;

    unsigned* my_ctr = &g_step[cta];
    unsigned* p0 = &g_step[bg * EGROUPS + 2 * w];
    unsigned* p1 = p0 + 1;
    const unsigned tgt0 = (unsigned)epoch * (T_SEQ + 1) + 1u;

    for (int idx = tid; idx < WROWS * (E_SZ / 4); idx += 256) {
        int j = idx >> 7;
        int kq = (idx & 127) << 2;
        int el = j / 3, gate = j - el * 3;
        *reinterpret_cast<float4*>(&sh_w[j * WSTR + kq]) =
            *reinterpret_cast<const float4*>(&Whh[(size_t)(gate * E_SZ + ebase + el) * E_SZ + kq]);
    }

    const float bh0 = bhh[0 * E_SZ + e];
    const float bh1 = bhh[1 * E_SZ + e];
    const float bh2 = bhh[2 * E_SZ + e];
    const int mylen = lens[bglob];

    hbuf[bglob * E_SZ + e] = 0.f;
    __syncthreads();
    if (tid == 0) ctr_release_add(my_ctr);

    const float* wp0 = sh_w + (jg * 3 + 0) * WSTR;
    const float* wp1 = wp0 + WSTR;
    const float* wp2 = wp1 + WSTR;
    float* sh_hs = sh_h + w * 512;

    float hprev = 0.f;
    float hnew = 0.f;

    for (int t = 0; t < T_SEQ; t++) {
        const float* xp = xproj + ((size_t)t * B_SZ + bglob) * G3E;
        float xr = xp[e];
        float xz = xp[E_SZ + e];
        float xn = xp[2 * E_SZ + e];

        ctr_wait(p0, tgt0 + (unsigned)t);
        ctr_wait(p1, tgt0 + (unsigned)t);

        {
            const float4* hb4 = reinterpret_cast<const float4*>(hbuf);
#pragma unroll
            for (int i = 0; i < 4; i++) {
                int f = jg + i * 32;
                int b = f >> 4, c4 = f & 15;
                float4 v = hb4[(bg * BTILE + b) * 128 + 16 * w + c4];
                *reinterpret_cast<float4*>(&sh_hs[b * 64 + c4 * 4]) = v;
            }
        }
        __syncwarp();

        unsigned long long a0[8], a1[8], a2[8];
#pragma unroll
        for (int b = 0; b < 8; b++) { a0[b] = 0ULL; a1[b] = 0ULL; a2[b] = 0ULL; }

#pragma unroll 4
        for (int kk = 0; kk < 16; kk++) {
            int k4 = kbase + kk * 4;
            int kl = kk * 4;
            ulonglong2 w0 = *reinterpret_cast<const ulonglong2*>(wp0 + k4);
            ulonglong2 w1 = *reinterpret_cast<const ulonglong2*>(wp1 + k4);
            ulonglong2 w2 = *reinterpret_cast<const ulonglong2*>(wp2 + k4);
#pragma unroll
            for (int b = 0; b < 8; b++) {
                ulonglong2 h2 = *reinterpret_cast<const ulonglong2*>(sh_hs + b * 64 + kl);
                fma2(a0[b], h2.x, w0.x); fma2(a0[b], h2.y, w0.y);
                fma2(a1[b], h2.x, w1.x); fma2(a1[b], h2.y, w1.y);
                fma2(a2[b], h2.x, w2.x); fma2(a2[b], h2.y, w2.y);
            }
        }

        __syncthreads();

#pragma unroll
        for (int b = 0; b < 8; b++) {
            sh_part[((w * 3 + 0) * 8 + b) * 32 + jg] = f32x2_sum(a0[b]);
            sh_part[((w * 3 + 1) * 8 + b) * 32 + jg] = f32x2_sum(a1[b]);
            sh_part[((w * 3 + 2) * 8 + b) * 32 + jg] = f32x2_sum(a2[b]);
        }
        __syncthreads();

        float s0 = 0.f, s1 = 0.f, s2 = 0.f;
#pragma unroll
        for (int ww = 0; ww < 8; ww++) {
            s0 += sh_part[((ww * 3 + 0) * 8 + w) * 32 + jg];
            s1 += sh_part[((ww * 3 + 1) * 8 + w) * 32 + jg];
            s2 += sh_part[((ww * 3 + 2) * 8 + w) * 32 + jg];
        }

        float hr = s0 + bh0, hz = s1 + bh1, hn = s2 + bh2;
        float r = __frcp_rn(1.f + __expf(-(xr + hr)));
        float z = __frcp_rn(1.f + __expf(-(xz + hz)));
        float te = __expf(2.f * (xn + r * hn));
        float n = (te - 1.f) * __frcp_rn(te + 1.f);
        bool m = (t < mylen);
        hnew = m ? ((1.f - z) * n + z * hprev) : hprev;
        hprev = hnew;

        hbuf[bglob * E_SZ + e] = hnew;
        __syncthreads();
        if (tid == 0) ctr_release_add(my_ctr);

        ybuf[((size_t)t * B_SZ + bglob) * E_SZ + e] = m ? hnew : 0.f;
    }

    finals[bglob * E_SZ + e] = hnew;
}

// ---------------- launch ----------------
extern "C" void kernel_launch(void* const* d_in, const int* in_sizes, int n_in,
                              void* d_out, int out_size) {
    const int*   input_batch = (const int*)d_in[0];
    const int*   lens        = (const int*)d_in[1];
    const float* emb         = (const float*)d_in[2];
    const float* W_ih        = (const float*)d_in[3];
    const float* W_hh        = (const float*)d_in[4];
    const float* b_ih        = (const float*)d_in[5];
    const float* b_hh        = (const float*)d_in[6];
    float* out = (float*)d_out;

    void* p;
    cudaGetSymbolAddress(&p, g_x);     float* gx  = (float*)p;
    cudaGetSymbolAddress(&p, g_xproj); float* gxp = (float*)p;
    cudaGetSymbolAddress(&p, g_h);     float* gh  = (float*)p;
    cudaGetSymbolAddress(&p, g_axhi);  __nv_bfloat16* axhi = (__nv_bfloat16*)p;
    cudaGetSymbolAddress(&p, g_axlo);  __nv_bfloat16* axlo = (__nv_bfloat16*)p;
    cudaGetSymbolAddress(&p, g_whi);   __nv_bfloat16* whi  = (__nv_bfloat16*)p;
    cudaGetSymbolAddress(&p, g_wlo);   __nv_bfloat16* wlo  = (__nv_bfloat16*)p;

    cudaFuncSetAttribute(gru_recur_kernel,
                         cudaFuncAttributeMaxDynamicSharedMemorySize, RSMEM_BYTES);

    const size_t out_x_elems = (size_t)T_SEQ * B_SZ * E_SZ;
    float* finals0 = out + out_x_elems;
    float* finals1 = out + out_x_elems + B_SZ * E_SZ;

    const int nx4 = M_ROWS * E_SZ / 4;
    const int nw4 = G3E * E_SZ / 4;

    {
        int total = T_SEQ * B_SZ * (E_SZ / 4);
        embed_kernel<<<(total + 255) / 256, 256>>>(input_batch, emb, gx);
    }

    // ---- layer 0 ----
    split_kernel<<<(nx4 + 255) / 256, 256>>>(gx, axhi, axlo, nx4);
    split_kernel<<<(nw4 + 255) / 256, 256>>>(W_ih, whi, wlo, nw4);
    tc_gemm<<<dim3(G3E / 128, M_ROWS / 128), 256>>>(axhi, axlo, whi, wlo, b_ih, gxp);
    gru_recur_kernel<<<RGRID, 256, RSMEM_BYTES>>>(gxp, W_hh, b_hh, lens, gh, gx, finals0, 0);

    // ---- layer 1 ----
    split_kernel<<<(nx4 + 255) / 256, 256>>>(gx, axhi, axlo, nx4);
    split_kernel<<<(nw4 + 255) / 256, 256>>>(W_ih + (size_t)G3E * E_SZ, whi, wlo, nw4);
    tc_gemm<<<dim3(G3E / 128, M_ROWS / 128), 256>>>(axhi, axlo, whi, wlo, b_ih + G3E, gxp);
    gru_recur_kernel<<<RGRID, 256, RSMEM_BYTES>>>(gxp, W_hh + (size_t)G3E * E_SZ,
                                                  b_hh + G3E, lens, gh, out, finals1, 1);
}